// round 16
// baseline (speedup 1.0000x reference)
#include <cuda_runtime.h>
#include <cstdint>

// Problem constants
#define BB 32
#define II 4096
#define VV 512
#define VTILE 128          // v per CTA (M)
#define CTA_I 32           // i per CTA -> K = 256
#define NCHUNK (II/CTA_I)  // 128 k-splits
#define NRED 8
#define NTHREADS 256
#define BSTRIDE 264        // floats per B row (256 data + 8 pad; %32==8 -> LDS.64 conflict-free)

__device__ float g_part[NCHUNK][BB * VV];   // split-K partials (8 MB)
__device__ float g_red[NRED][BB * VV];      // second-stage partials

// fp32 -> tf32 with round-to-nearest (unbiased; rel err <= 2^-11)
__device__ __forceinline__ uint32_t f2tf(float f) {
    uint32_t r;
    asm("cvt.rna.tf32.f32 %0, %1;" : "=r"(r) : "f"(f));
    return r;
}

__device__ __forceinline__ void mma_tf32(float* c, const uint32_t* a,
                                         const uint32_t* b) {
    asm volatile(
        "mma.sync.aligned.m16n8k8.row.col.f32.tf32.tf32.f32 "
        "{%0,%1,%2,%3}, {%4,%5,%6,%7}, {%8,%9}, {%0,%1,%2,%3};"
        : "+f"(c[0]), "+f"(c[1]), "+f"(c[2]), "+f"(c[3])
        : "r"(a[0]), "r"(a[1]), "r"(a[2]), "r"(a[3]), "r"(b[0]), "r"(b[1]));
}

// D[v_local, b] = sum_k A[v_local,k]*B[k,b].
// A (=W) streamed straight from GMEM (zero reuse; no smem, no barriers).
// B (=x) converted to tf32 ONCE at staging and stored pair-ordered
// [k, k+4] so each fragment is one conflict-free LDS.64.
__global__ void __launch_bounds__(NTHREADS)
caps_mma_kernel(const float4* __restrict__ x4, const float* __restrict__ w) {
    __shared__ uint32_t Bsm[BB * BSTRIDE];   // 33.8 KB, tf32 values

    const int tid  = threadIdx.x;
    const int wrp  = tid >> 5;        // warp 0..7 -> m rows [wrp*16, wrp*16+16)
    const int lane = tid & 31;
    const int g    = lane >> 2;       // groupID 0..7
    const int t    = lane & 3;        // threadID-in-group 0..3
    const int v0   = blockIdx.x * VTILE;
    const int i0   = blockIdx.y * CTA_I;

    // ---- stage B once: convert + pair-reorder; 1024 (b,il) blocks, 4/thread ----
    #pragma unroll
    for (int j = 0; j < 4; ++j) {
        const int p  = tid + j * NTHREADS;   // 0..1023
        const int b  = p >> 5;
        const int il = p & 31;
        const size_t f4 = (size_t)b * 8192 + (size_t)(i0 + il) * 2;
        float4 xa = x4[f4], xb = x4[f4 + 1];
        uint32_t cva[8] = { f2tf(xa.x), f2tf(xa.y), f2tf(xa.z), f2tf(xa.w),
                            f2tf(xb.x), f2tf(xb.y), f2tf(xb.z), f2tf(xb.w) };
        uint32_t* dst = &Bsm[b * BSTRIDE + il * 8];
        // pair order: [k0,k4, k1,k5, k2,k6, k3,k7]
        *(uint4*)(dst)     = make_uint4(cva[0], cva[4], cva[1], cva[5]);
        *(uint4*)(dst + 4) = make_uint4(cva[2], cva[6], cva[3], cva[7]);
    }

    float c[4][4];
    #pragma unroll
    for (int nt = 0; nt < 4; ++nt)
        #pragma unroll
        for (int j = 0; j < 4; ++j) c[nt][j] = 0.f;

    const int row = wrp * 16 + g;                             // A row (v_local)
    const float* wp = w + ((size_t)i0 * 512 + v0 + row) * 8;  // W[i0][v0+row][0]

    __syncthreads();   // the only barrier: tf32-B resident

    // ---- mainloop: 32 i's, K=8 each; no syncs, warps fully decoupled ----
    #pragma unroll 16
    for (int il = 0; il < CTA_I; ++il) {
        // A fragment direct from GMEM: rows row, row+8; cols t, t+4 (d-dim)
        const float* ap = wp + (size_t)il * 4096;   // W[i0+il][v0+row][0]
        uint32_t a[4] = { f2tf(ap[t]), f2tf(ap[64 + t]),
                          f2tf(ap[t + 4]), f2tf(ap[64 + t + 4]) };
        #pragma unroll
        for (int nt = 0; nt < 4; ++nt) {
            // one LDS.64: {b(k=il*8+t), b(k=il*8+t+4)} for col n = nt*8+g
            const uint2 bq =
                *(const uint2*)&Bsm[(nt * 8 + g) * BSTRIDE + il * 8 + t * 2];
            uint32_t b[2] = { bq.x, bq.y };
            mma_tf32(c[nt], a, b);
        }
    }

    // ---- epilogue: scatter accumulators to split-K partials ----
    float* outp = &g_part[blockIdx.y][0];
    #pragma unroll
    for (int nt = 0; nt < 4; ++nt) {
        const int bc = nt * 8 + t * 2;
        outp[(size_t)bc * VV + v0 + row]           = c[nt][0];
        outp[(size_t)(bc + 1) * VV + v0 + row]     = c[nt][1];
        outp[(size_t)bc * VV + v0 + row + 8]       = c[nt][2];
        outp[(size_t)(bc + 1) * VV + v0 + row + 8] = c[nt][3];
    }
}

// First-stage reduction: 256 blocks, each folds 16 chunks for one b.
__global__ void __launch_bounds__(256)
caps_reduce_kernel() {
    const int b   = blockIdx.x;   // 0..31
    const int s   = blockIdx.y;   // 0..NRED-1
    const int tid = threadIdx.x;
    #pragma unroll
    for (int j = 0; j < 2; ++j) {
        const int v = tid + j * 256;
        float acc = 0.f;
        #pragma unroll
        for (int cc = 0; cc < NCHUNK / NRED; ++cc)
            acc += g_part[s * (NCHUNK / NRED) + cc][b * VV + v];
        g_red[s][b * VV + v] = acc;
    }
}

// Final: fold NRED partials, squash, write (t, outputs) — identical halves.
__global__ void __launch_bounds__(256)
caps_finish_kernel(float* __restrict__ out, int out_size) {
    const int b   = blockIdx.x;
    const int tid = threadIdx.x;
    __shared__ float red[256];

    float local[2];
    #pragma unroll
    for (int j = 0; j < 2; ++j) {
        const int v = tid + j * 256;
        float acc = 0.f;
        #pragma unroll
        for (int cc = 0; cc < NRED; ++cc) acc += g_red[cc][b * VV + v];
        local[j] = acc;
    }

    float sq = local[0] * local[0] + local[1] * local[1];
    red[tid] = sq;
    __syncthreads();
    for (int off = 128; off; off >>= 1) {
        if (tid < off) red[tid] += red[tid + off];
        __syncthreads();
    }
    const float total = red[0];
    const float scale = total / ((1.0f + total) * sqrtf(total));

    #pragma unroll
    for (int j = 0; j < 2; ++j) {
        const int v   = tid + j * 256;
        const float o = local[j] * scale;
        const int idx = b * VV + v;
        if (idx < out_size) out[idx] = o;                       // t
        if (idx + BB * VV < out_size) out[idx + BB * VV] = o;   // outputs
    }
}

extern "C" void kernel_launch(void* const* d_in, const int* in_sizes, int n_in,
                              void* d_out, int out_size) {
    const float4* x4 = (const float4*)d_in[0];  // x: [32, 4096, 8] fp32
    const float*  w  = (const float*)d_in[1];   // W: [1, 4096, 512, 8] fp32
    float* out = (float*)d_out;

    dim3 grid1(VV / VTILE, NCHUNK);  // (4, 128) = 512 CTAs
    caps_mma_kernel<<<grid1, NTHREADS>>>(x4, w);
    caps_reduce_kernel<<<dim3(BB, NRED), 256>>>();
    caps_finish_kernel<<<BB, 256>>>(out, out_size);
}